// round 5
// baseline (speedup 1.0000x reference)
#include <cuda_runtime.h>
#include <cstdint>

// Problem sizes (fixed by the reference)
#define B_SZ 2
#define N_SZ 1024
#define L_SZ 4096
#define C_SZ 1024
#define H_SZ 16
#define D_SZ 64
#define M_KEYS (N_SZ + L_SZ)   // 5120
#define C2 (2 * C_SZ)          // 2048
#define C3 (3 * C_SZ)          // 3072

// Scratch (static device globals — no allocation in kernel_launch)
__device__ float g_Xo  [B_SZ * N_SZ * C_SZ];   // tf32-rounded x_obj
__device__ float g_Xc  [B_SZ * L_SZ * C_SZ];   // tf32-rounded x_ctx
__device__ float g_QKV [B_SZ * N_SZ * C3];     // [B,N, q|k|v]
__device__ float g_KVc [B_SZ * L_SZ * C2];     // [B,L,2C]
__device__ float g_Ctx [B_SZ * N_SZ * C_SZ];   // attention output (tf32-rounded)
__device__ float g_WT    [C3 * C_SZ];          // [WqT ; WkvT]  (tf32-rounded)
__device__ float g_WprojT[C_SZ * C_SZ];        // Wproj^T       (tf32-rounded)

// ---------------------------------------------------------------------------
// Helpers (sm_80-era PTX — assembles under compute_103 virtual arch)
// ---------------------------------------------------------------------------
__device__ __forceinline__ uint32_t smem_u32(const void* p) {
    uint32_t a;
    asm("{ .reg .u64 t; cvta.to.shared.u64 t, %1; cvt.u32.u64 %0, t; }"
        : "=r"(a) : "l"(p));
    return a;
}
__device__ __forceinline__ uint32_t f2tf32(float f) {
    uint32_t r;
    asm("cvt.rna.tf32.f32 %0, %1;" : "=r"(r) : "f"(f));
    return r;
}
__device__ __forceinline__ float f2tf32f(float f) {
    return __uint_as_float(f2tf32(f));
}
__device__ __forceinline__ void cp16(uint32_t dst, const float* src) {
    asm volatile("cp.async.ca.shared.global [%0], [%1], 16;"
                 :: "r"(dst), "l"(src));
}
__device__ __forceinline__ void mma_tf32(float* d, const uint32_t* a,
                                         uint32_t b0, uint32_t b1) {
    asm volatile(
        "mma.sync.aligned.m16n8k8.row.col.f32.tf32.tf32.f32 "
        "{%0,%1,%2,%3}, {%4,%5,%6,%7}, {%8,%9}, {%0,%1,%2,%3};"
        : "+f"(d[0]), "+f"(d[1]), "+f"(d[2]), "+f"(d[3])
        : "r"(a[0]), "r"(a[1]), "r"(a[2]), "r"(a[3]), "r"(b0), "r"(b1));
}

// ---------------------------------------------------------------------------
// Elementwise tf32 round-copy (float4 vectorized)
// ---------------------------------------------------------------------------
__global__ __launch_bounds__(256)
void round_copy(const float4* __restrict__ in, float4* __restrict__ out, int n4)
{
    int i = blockIdx.x * 256 + threadIdx.x;
    int stride = gridDim.x * 256;
    for (; i < n4; i += stride) {
        float4 v = in[i];
        float4 w;
        w.x = f2tf32f(v.x); w.y = f2tf32f(v.y);
        w.z = f2tf32f(v.z); w.w = f2tf32f(v.w);
        out[i] = w;
    }
}

// ---------------------------------------------------------------------------
// Weight transpose + tf32 round: out[c][r] = tf32(in[r][c]).
// ---------------------------------------------------------------------------
__global__ __launch_bounds__(256)
void transpose_w(const float* __restrict__ in, float* __restrict__ out,
                 int R, int Ccols)
{
    __shared__ float t[32][33];
    int c0 = blockIdx.x * 32, r0 = blockIdx.y * 32;
    #pragma unroll
    for (int j = threadIdx.y; j < 32; j += 8)
        t[j][threadIdx.x] = in[(size_t)(r0 + j) * Ccols + c0 + threadIdx.x];
    __syncthreads();
    #pragma unroll
    for (int j = threadIdx.y; j < 32; j += 8)
        out[(size_t)(c0 + j) * R + r0 + threadIdx.x] = f2tf32f(t[threadIdx.x][j]);
}

// ---------------------------------------------------------------------------
// TF32 tensor-core GEMM:  C[M,N] = A[M,K] @ BT[N,K]^T  (+ bias)
// All operands PRE-ROUNDED to tf32 — no cvt in the mainloop.
// ---------------------------------------------------------------------------
#define BKC 16
#define APAD 20
#define TILE_W (128 * APAD)

__global__ __launch_bounds__(256, 2)
void gemm_mma(int M, int N, int K,
              const float* __restrict__ A, const float* __restrict__ BT,
              float* __restrict__ C, const float* __restrict__ bias)
{
    __shared__ float sm[4 * TILE_W];

    const int tid  = threadIdx.x;
    const int wid  = tid >> 5, lane = tid & 31;
    const int grp  = lane >> 2, qid = lane & 3;
    const int bm   = blockIdx.y * 128, bn = blockIdx.x * 128;
    const int wm   = (wid & 3) * 32;
    const int wn   = (wid >> 2) * 64;

    const uint32_t sbase = smem_u32(sm);
    const int m_ld = tid >> 2;
    const int q_ld = (tid & 3) * 4;

    float acc[2][8][4];
    #pragma unroll
    for (int i = 0; i < 2; ++i)
        #pragma unroll
        for (int j = 0; j < 8; ++j)
            #pragma unroll
            for (int q = 0; q < 4; ++q) acc[i][j][q] = 0.0f;

    const float* Abase = A  + (size_t)bm * K;
    const float* Bbase = BT + (size_t)bn * K;

    auto load_tile = [&](int c, int stg) {
        uint32_t as = sbase + (uint32_t)(stg * 2 * TILE_W) * 4u;
        uint32_t bs = as + (uint32_t)TILE_W * 4u;
        const float* Ag = Abase + (size_t)c * BKC;
        const float* Bg = Bbase + (size_t)c * BKC;
        #pragma unroll
        for (int i = 0; i < 2; ++i) {
            int m = m_ld + i * 64;
            cp16(as + (uint32_t)(m * APAD + q_ld) * 4u, Ag + (size_t)m * K + q_ld);
            cp16(bs + (uint32_t)(m * APAD + q_ld) * 4u, Bg + (size_t)m * K + q_ld);
        }
    };

    load_tile(0, 0);
    asm volatile("cp.async.commit_group;");

    const int NC = K / BKC;
    for (int c = 0; c < NC; ++c) {
        if (c + 1 < NC) {
            load_tile(c + 1, (c + 1) & 1);
            asm volatile("cp.async.commit_group;");
            asm volatile("cp.async.wait_group 1;");
        } else {
            asm volatile("cp.async.wait_group 0;");
        }
        __syncthreads();

        const float* As = sm + (c & 1) * 2 * TILE_W;
        const float* Bs = As + TILE_W;
        #pragma unroll
        for (int kk = 0; kk < BKC; kk += 8) {
            uint32_t at[2][4];
            #pragma unroll
            for (int mf = 0; mf < 2; ++mf) {
                int r0 = wm + mf * 16 + grp;
                at[mf][0] = __float_as_uint(As[r0 * APAD + kk + qid]);
                at[mf][1] = __float_as_uint(As[(r0 + 8) * APAD + kk + qid]);
                at[mf][2] = __float_as_uint(As[r0 * APAD + kk + qid + 4]);
                at[mf][3] = __float_as_uint(As[(r0 + 8) * APAD + kk + qid + 4]);
            }
            #pragma unroll
            for (int nf = 0; nf < 8; ++nf) {
                int cn = wn + nf * 8 + grp;
                uint32_t b0 = __float_as_uint(Bs[cn * APAD + kk + qid]);
                uint32_t b1 = __float_as_uint(Bs[cn * APAD + kk + qid + 4]);
                mma_tf32(acc[0][nf], at[0], b0, b1);
                mma_tf32(acc[1][nf], at[1], b0, b1);
            }
        }
        __syncthreads();
    }

    #pragma unroll
    for (int mf = 0; mf < 2; ++mf) {
        int r0 = bm + wm + mf * 16 + grp;
        #pragma unroll
        for (int nf = 0; nf < 8; ++nf) {
            int cc = bn + wn + nf * 8 + qid * 2;
            float b0 = 0.0f, b1 = 0.0f;
            if (bias != nullptr) { b0 = bias[cc]; b1 = bias[cc + 1]; }
            float2 v0; v0.x = acc[mf][nf][0] + b0; v0.y = acc[mf][nf][1] + b1;
            float2 v1; v1.x = acc[mf][nf][2] + b0; v1.y = acc[mf][nf][3] + b1;
            *reinterpret_cast<float2*>(C + (size_t)r0 * N + cc) = v0;
            *reinterpret_cast<float2*>(C + (size_t)(r0 + 8) * N + cc) = v1;
        }
    }
}

// ---------------------------------------------------------------------------
// Flash attention on tensor cores (tf32 mma.sync).
// Q/K(obj)/V(obj) come from fused QKV buffer (row stride C3);
// K(ctx)/V(ctx) from KVc (row stride C2). V row = K row + C_SZ in both.
// ---------------------------------------------------------------------------
#define QPAD 68
#define VPAD 72
#define FA_SMEM ((128 * QPAD + 64 * QPAD + 64 * VPAD + 128 * QPAD) * 4)

__global__ __launch_bounds__(256, 2)
void flash_mma(const float* __restrict__ QKV,
               const float* __restrict__ KVc,
               float* __restrict__ Ctx)
{
    extern __shared__ float sm[];
    float* Qs = sm;                       // [128][QPAD]
    float* Ks = Qs + 128 * QPAD;          // [64][QPAD]
    float* Vs = Ks + 64 * QPAD;           // [64][VPAD]
    float* Ps = Vs + 64 * VPAD;           // [128][QPAD]

    const int tid  = threadIdx.x;
    const int wid  = tid >> 5, lane = tid & 31;
    const int grp  = lane >> 2, qid = lane & 3;
    const int wm   = wid * 16;
    const int qt   = blockIdx.x;
    const int h    = blockIdx.y;
    const int b    = blockIdx.z;

    const float scale = 0.125f;

    // Load Q tile [128][64] from QKV (cols 0..1023), scale + tf32-round once
    const float* Qg = QKV + ((size_t)b * N_SZ + (size_t)qt * 128) * C3 + h * D_SZ;
    #pragma unroll
    for (int r = 0; r < 8; ++r) {
        int fid = tid + r * 256;
        int m   = fid >> 4;
        int ds  = (fid & 15) * 4;
        float4 v = *reinterpret_cast<const float4*>(Qg + (size_t)m * C3 + ds);
        float4 w;
        w.x = f2tf32f(v.x * scale);
        w.y = f2tf32f(v.y * scale);
        w.z = f2tf32f(v.z * scale);
        w.w = f2tf32f(v.w * scale);
        *reinterpret_cast<float4*>(&Qs[m * QPAD + ds]) = w;
    }

    float o[8][4];
    #pragma unroll
    for (int nf = 0; nf < 8; ++nf)
        #pragma unroll
        for (int q = 0; q < 4; ++q) o[nf][q] = 0.0f;
    float mi[2] = {-1e30f, -1e30f};
    float li[2] = {0.0f, 0.0f};

    for (int kt = 0; kt < M_KEYS / 64; ++kt) {
        const float* Kg;
        int kstride;
        if (kt < N_SZ / 64) {
            Kg = QKV + ((size_t)b * N_SZ + (size_t)kt * 64) * C3 + C_SZ + h * D_SZ;
            kstride = C3;
        } else {
            Kg = KVc + ((size_t)b * L_SZ + ((size_t)kt * 64 - N_SZ)) * C2 + h * D_SZ;
            kstride = C2;
        }
        const float* Vg = Kg + C_SZ;

        __syncthreads();

        #pragma unroll
        for (int r = 0; r < 4; ++r) {
            int fid = tid + r * 256;
            int n   = fid >> 4;
            int ds  = (fid & 15) * 4;
            float4 kv = *reinterpret_cast<const float4*>(Kg + (size_t)n * kstride + ds);
            float4 kw;
            kw.x = f2tf32f(kv.x); kw.y = f2tf32f(kv.y);
            kw.z = f2tf32f(kv.z); kw.w = f2tf32f(kv.w);
            *reinterpret_cast<float4*>(&Ks[n * QPAD + ds]) = kw;
            float4 vv = *reinterpret_cast<const float4*>(Vg + (size_t)n * kstride + ds);
            float4 vw;
            vw.x = f2tf32f(vv.x); vw.y = f2tf32f(vv.y);
            vw.z = f2tf32f(vv.z); vw.w = f2tf32f(vv.w);
            *reinterpret_cast<float4*>(&Vs[n * VPAD + ds]) = vw;
        }
        __syncthreads();

        // S = Qs @ Ks^T : per-warp m16 x n64 x k64
        float s[8][4];
        #pragma unroll
        for (int nf = 0; nf < 8; ++nf)
            #pragma unroll
            for (int q = 0; q < 4; ++q) s[nf][q] = 0.0f;

        #pragma unroll
        for (int kk = 0; kk < 8; ++kk) {
            uint32_t a[4];
            const int r0 = (wm + grp) * QPAD + kk * 8 + qid;
            const int r1 = (wm + grp + 8) * QPAD + kk * 8 + qid;
            a[0] = __float_as_uint(Qs[r0]);
            a[1] = __float_as_uint(Qs[r1]);
            a[2] = __float_as_uint(Qs[r0 + 4]);
            a[3] = __float_as_uint(Qs[r1 + 4]);
            #pragma unroll
            for (int nf = 0; nf < 8; ++nf) {
                const int cn = (nf * 8 + grp) * QPAD + kk * 8 + qid;
                uint32_t b0 = __float_as_uint(Ks[cn]);
                uint32_t b1 = __float_as_uint(Ks[cn + 4]);
                mma_tf32(s[nf], a, b0, b1);
            }
        }

        // Online softmax
        float mx0 = -1e30f, mx1 = -1e30f;
        #pragma unroll
        for (int nf = 0; nf < 8; ++nf) {
            mx0 = fmaxf(mx0, fmaxf(s[nf][0], s[nf][1]));
            mx1 = fmaxf(mx1, fmaxf(s[nf][2], s[nf][3]));
        }
        #pragma unroll
        for (int off = 1; off < 4; off <<= 1) {
            mx0 = fmaxf(mx0, __shfl_xor_sync(0xffffffffu, mx0, off));
            mx1 = fmaxf(mx1, __shfl_xor_sync(0xffffffffu, mx1, off));
        }
        float mnew0 = fmaxf(mi[0], mx0);
        float mnew1 = fmaxf(mi[1], mx1);
        float corr0 = __expf(mi[0] - mnew0);
        float corr1 = __expf(mi[1] - mnew1);
        float sum0 = 0.0f, sum1 = 0.0f;
        #pragma unroll
        for (int nf = 0; nf < 8; ++nf) {
            s[nf][0] = __expf(s[nf][0] - mnew0);
            s[nf][1] = __expf(s[nf][1] - mnew0);
            s[nf][2] = __expf(s[nf][2] - mnew1);
            s[nf][3] = __expf(s[nf][3] - mnew1);
            sum0 += s[nf][0] + s[nf][1];
            sum1 += s[nf][2] + s[nf][3];
        }
        #pragma unroll
        for (int off = 1; off < 4; off <<= 1) {
            sum0 += __shfl_xor_sync(0xffffffffu, sum0, off);
            sum1 += __shfl_xor_sync(0xffffffffu, sum1, off);
        }
        li[0] = li[0] * corr0 + sum0;
        li[1] = li[1] * corr1 + sum1;
        mi[0] = mnew0;
        mi[1] = mnew1;
        #pragma unroll
        for (int nf = 0; nf < 8; ++nf) {
            o[nf][0] *= corr0;
            o[nf][1] *= corr0;
            o[nf][2] *= corr1;
            o[nf][3] *= corr1;
        }

        // P -> SMEM (tf32-rounded), relayout C-frag -> A-frag
        #pragma unroll
        for (int nf = 0; nf < 8; ++nf) {
            float2 p0, p1;
            p0.x = f2tf32f(s[nf][0]); p0.y = f2tf32f(s[nf][1]);
            p1.x = f2tf32f(s[nf][2]); p1.y = f2tf32f(s[nf][3]);
            *reinterpret_cast<float2*>(&Ps[(wm + grp) * QPAD + nf * 8 + qid * 2]) = p0;
            *reinterpret_cast<float2*>(&Ps[(wm + grp + 8) * QPAD + nf * 8 + qid * 2]) = p1;
        }
        __syncthreads();

        // O += P @ V
        #pragma unroll
        for (int kk = 0; kk < 8; ++kk) {
            uint32_t a[4];
            const int r0 = (wm + grp) * QPAD + kk * 8 + qid;
            const int r1 = (wm + grp + 8) * QPAD + kk * 8 + qid;
            a[0] = __float_as_uint(Ps[r0]);
            a[1] = __float_as_uint(Ps[r1]);
            a[2] = __float_as_uint(Ps[r0 + 4]);
            a[3] = __float_as_uint(Ps[r1 + 4]);
            #pragma unroll
            for (int nf = 0; nf < 8; ++nf) {
                const int cb = (kk * 8 + qid) * VPAD + nf * 8 + grp;
                uint32_t b0 = __float_as_uint(Vs[cb]);
                uint32_t b1 = __float_as_uint(Vs[cb + 4 * VPAD]);
                mma_tf32(o[nf], a, b0, b1);
            }
        }
    }

    // Epilogue: normalize, tf32-round (Ctx feeds the tf32 out-proj), store
    const float inv0 = 1.0f / li[0];
    const float inv1 = 1.0f / li[1];
    float* Og = Ctx + ((size_t)b * N_SZ + (size_t)qt * 128) * C_SZ + h * D_SZ;
    #pragma unroll
    for (int nf = 0; nf < 8; ++nf) {
        int col = nf * 8 + qid * 2;
        float2 v0, v1;
        v0.x = f2tf32f(o[nf][0] * inv0); v0.y = f2tf32f(o[nf][1] * inv0);
        v1.x = f2tf32f(o[nf][2] * inv1); v1.y = f2tf32f(o[nf][3] * inv1);
        *reinterpret_cast<float2*>(Og + (size_t)(wm + grp) * C_SZ + col) = v0;
        *reinterpret_cast<float2*>(Og + (size_t)(wm + grp + 8) * C_SZ + col) = v1;
    }
}

// ---------------------------------------------------------------------------
extern "C" void kernel_launch(void* const* d_in, const int* in_sizes, int n_in,
                              void* d_out, int out_size)
{
    const float* x_obj = (const float*)d_in[0];
    const float* x_ctx = (const float*)d_in[1];
    const float* Wq    = (const float*)d_in[2];
    const float* Wkv   = (const float*)d_in[3];
    const float* Wproj = (const float*)d_in[4];
    const float* bproj = (const float*)d_in[5];
    float* out = (float*)d_out;

    float *pXo, *pXc, *pQKV, *pKVc, *pCtx, *pWT, *pWprojT;
    cudaGetSymbolAddress((void**)&pXo,     g_Xo);
    cudaGetSymbolAddress((void**)&pXc,     g_Xc);
    cudaGetSymbolAddress((void**)&pQKV,    g_QKV);
    cudaGetSymbolAddress((void**)&pKVc,    g_KVc);
    cudaGetSymbolAddress((void**)&pCtx,    g_Ctx);
    cudaGetSymbolAddress((void**)&pWT,     g_WT);
    cudaGetSymbolAddress((void**)&pWprojT, g_WprojT);

    cudaFuncSetAttribute(flash_mma, cudaFuncAttributeMaxDynamicSharedMemorySize, FA_SMEM);

    // Weight transposes + tf32 round ([K,N] -> [N,K])
    transpose_w<<<dim3(C_SZ / 32, C_SZ / 32), dim3(32, 8)>>>(Wq, pWT, C_SZ, C_SZ);
    transpose_w<<<dim3(C2 / 32, C_SZ / 32), dim3(32, 8)>>>(Wkv, pWT + C_SZ * C_SZ, C_SZ, C2);
    transpose_w<<<dim3(C_SZ / 32, C_SZ / 32), dim3(32, 8)>>>(Wproj, pWprojT, C_SZ, C_SZ);

    // tf32 round-copies of activations
    round_copy<<<512, 256>>>((const float4*)x_obj, (float4*)pXo,
                             B_SZ * N_SZ * C_SZ / 4);
    round_copy<<<1024, 256>>>((const float4*)x_ctx, (float4*)pXc,
                              B_SZ * L_SZ * C_SZ / 4);

    // Fused Q+KV projection of x_obj: [2048,1024] x [1024,3072]
    gemm_mma<<<dim3(C3 / 128, 2048 / 128), 256>>>(
        2048, C3, 1024, pXo, pWT, pQKV, nullptr);
    // KV projection of x_ctx: [8192,1024] x [1024,2048]
    gemm_mma<<<dim3(C2 / 128, 8192 / 128), 256>>>(
        8192, C2, 1024, pXc, pWT + C_SZ * C_SZ, pKVc, nullptr);

    // Attention (tensor-core tf32 flash)
    flash_mma<<<dim3(N_SZ / 128, H_SZ, B_SZ), 256, FA_SMEM>>>(pQKV, pKVc, pCtx);

    // Output projection + bias
    gemm_mma<<<dim3(1024 / 128, 2048 / 128), 256>>>(
        2048, 1024, 1024, pCtx, pWprojT, out, bproj);
}

// round 6
// speedup vs baseline: 1.0087x; 1.0087x over previous
#include <cuda_runtime.h>
#include <cstdint>

// Problem sizes (fixed by the reference)
#define B_SZ 2
#define N_SZ 1024
#define L_SZ 4096
#define C_SZ 1024
#define H_SZ 16
#define D_SZ 64
#define M_KEYS (N_SZ + L_SZ)   // 5120
#define C2 (2 * C_SZ)          // 2048
#define C3 (3 * C_SZ)          // 3072

// Scratch (static device globals — no allocation in kernel_launch)
__device__ float g_Xo  [B_SZ * N_SZ * C_SZ];   // tf32-rounded x_obj
__device__ float g_Xc  [B_SZ * L_SZ * C_SZ];   // tf32-rounded x_ctx
__device__ float g_QKV [B_SZ * N_SZ * C3];     // [B,N, q|k|v]
__device__ float g_KVc [B_SZ * L_SZ * C2];     // [B,L,2C]
__device__ float g_Ctx [B_SZ * N_SZ * C_SZ];   // attention output (tf32-rounded)
__device__ float g_WT    [C3 * C_SZ];          // [WqT ; WkvT]  (tf32-rounded)
__device__ float g_WprojT[C_SZ * C_SZ];        // Wproj^T       (tf32-rounded)

// ---------------------------------------------------------------------------
// Helpers
// ---------------------------------------------------------------------------
__device__ __forceinline__ uint32_t smem_u32(const void* p) {
    uint32_t a;
    asm("{ .reg .u64 t; cvta.to.shared.u64 t, %1; cvt.u32.u64 %0, t; }"
        : "=r"(a) : "l"(p));
    return a;
}
__device__ __forceinline__ uint32_t f2tf32(float f) {
    uint32_t r;
    asm("cvt.rna.tf32.f32 %0, %1;" : "=r"(r) : "f"(f));
    return r;
}
__device__ __forceinline__ float f2tf32f(float f) {
    return __uint_as_float(f2tf32(f));
}
__device__ __forceinline__ void cp16(uint32_t dst, const float* src) {
    asm volatile("cp.async.ca.shared.global [%0], [%1], 16;"
                 :: "r"(dst), "l"(src));
}
// NOTE: NOT volatile — pure register op; lets ptxas hoist/batch LDS and hide
// shared-memory latency under MMA issue.
__device__ __forceinline__ void mma_tf32(float* d, const uint32_t* a,
                                         uint32_t b0, uint32_t b1) {
    asm("mma.sync.aligned.m16n8k8.row.col.f32.tf32.tf32.f32 "
        "{%0,%1,%2,%3}, {%4,%5,%6,%7}, {%8,%9}, {%0,%1,%2,%3};"
        : "+f"(d[0]), "+f"(d[1]), "+f"(d[2]), "+f"(d[3])
        : "r"(a[0]), "r"(a[1]), "r"(a[2]), "r"(a[3]), "r"(b0), "r"(b1));
}

// ---------------------------------------------------------------------------
// Elementwise tf32 round-copy (float4 vectorized)
// ---------------------------------------------------------------------------
__global__ __launch_bounds__(256)
void round_copy(const float4* __restrict__ in, float4* __restrict__ out, int n4)
{
    int i = blockIdx.x * 256 + threadIdx.x;
    int stride = gridDim.x * 256;
    for (; i < n4; i += stride) {
        float4 v = in[i];
        float4 w;
        w.x = f2tf32f(v.x); w.y = f2tf32f(v.y);
        w.z = f2tf32f(v.z); w.w = f2tf32f(v.w);
        out[i] = w;
    }
}

// ---------------------------------------------------------------------------
// Weight transpose + tf32 round: out[c][r] = tf32(in[r][c]).
// ---------------------------------------------------------------------------
__global__ __launch_bounds__(256)
void transpose_w(const float* __restrict__ in, float* __restrict__ out,
                 int R, int Ccols)
{
    __shared__ float t[32][33];
    int c0 = blockIdx.x * 32, r0 = blockIdx.y * 32;
    #pragma unroll
    for (int j = threadIdx.y; j < 32; j += 8)
        t[j][threadIdx.x] = in[(size_t)(r0 + j) * Ccols + c0 + threadIdx.x];
    __syncthreads();
    #pragma unroll
    for (int j = threadIdx.y; j < 32; j += 8)
        out[(size_t)(c0 + j) * R + r0 + threadIdx.x] = f2tf32f(t[threadIdx.x][j]);
}

// ---------------------------------------------------------------------------
// TF32 tensor-core GEMM:  C[M,N] = A[M,K] @ BT[N,K]^T  (+ bias)
// Pre-rounded operands. 3-stage cp.async pipeline, one sync per chunk.
// Frag loads batched ahead of MMA issue (latency hiding).
// ---------------------------------------------------------------------------
#define BKC 16
#define APAD 20
#define TILE_W (128 * APAD)
#define STAGES 3
#define GEMM_SMEM (STAGES * 2 * TILE_W * 4)

__global__ __launch_bounds__(256, 2)
void gemm_mma(int M, int N, int K,
              const float* __restrict__ A, const float* __restrict__ BT,
              float* __restrict__ C, const float* __restrict__ bias)
{
    extern __shared__ float sm[];

    const int tid  = threadIdx.x;
    const int wid  = tid >> 5, lane = tid & 31;
    const int grp  = lane >> 2, qid = lane & 3;
    const int bm   = blockIdx.y * 128, bn = blockIdx.x * 128;
    const int wm   = (wid & 3) * 32;
    const int wn   = (wid >> 2) * 64;

    const uint32_t sbase = smem_u32(sm);
    const int m_ld = tid >> 2;
    const int q_ld = (tid & 3) * 4;

    float acc[2][8][4];
    #pragma unroll
    for (int i = 0; i < 2; ++i)
        #pragma unroll
        for (int j = 0; j < 8; ++j)
            #pragma unroll
            for (int q = 0; q < 4; ++q) acc[i][j][q] = 0.0f;

    const float* Abase = A  + (size_t)bm * K;
    const float* Bbase = BT + (size_t)bn * K;

    auto load_tile = [&](int c, int stg) {
        uint32_t as = sbase + (uint32_t)(stg * 2 * TILE_W) * 4u;
        uint32_t bs = as + (uint32_t)TILE_W * 4u;
        const float* Ag = Abase + (size_t)c * BKC;
        const float* Bg = Bbase + (size_t)c * BKC;
        #pragma unroll
        for (int i = 0; i < 2; ++i) {
            int m = m_ld + i * 64;
            cp16(as + (uint32_t)(m * APAD + q_ld) * 4u, Ag + (size_t)m * K + q_ld);
            cp16(bs + (uint32_t)(m * APAD + q_ld) * 4u, Bg + (size_t)m * K + q_ld);
        }
    };

    const int NC = K / BKC;
    load_tile(0, 0);
    asm volatile("cp.async.commit_group;");
    load_tile(1, 1);
    asm volatile("cp.async.commit_group;");

    for (int c = 0; c < NC; ++c) {
        if (c + 2 < NC) {
            asm volatile("cp.async.wait_group 1;");
        } else {
            asm volatile("cp.async.wait_group 0;");
        }
        __syncthreads();
        if (c + 2 < NC) {
            load_tile(c + 2, (c + 2) % STAGES);
            asm volatile("cp.async.commit_group;");
        }

        const float* As = sm + (c % STAGES) * 2 * TILE_W;
        const float* Bs = As + TILE_W;
        #pragma unroll
        for (int kk = 0; kk < BKC; kk += 8) {
            // Batch all fragment loads for this k-step
            uint32_t at[2][4];
            #pragma unroll
            for (int mf = 0; mf < 2; ++mf) {
                int r0 = wm + mf * 16 + grp;
                at[mf][0] = __float_as_uint(As[r0 * APAD + kk + qid]);
                at[mf][1] = __float_as_uint(As[(r0 + 8) * APAD + kk + qid]);
                at[mf][2] = __float_as_uint(As[r0 * APAD + kk + qid + 4]);
                at[mf][3] = __float_as_uint(As[(r0 + 8) * APAD + kk + qid + 4]);
            }
            uint32_t bt[8][2];
            #pragma unroll
            for (int nf = 0; nf < 8; ++nf) {
                int cn = wn + nf * 8 + grp;
                bt[nf][0] = __float_as_uint(Bs[cn * APAD + kk + qid]);
                bt[nf][1] = __float_as_uint(Bs[cn * APAD + kk + qid + 4]);
            }
            // Then issue all MMAs
            #pragma unroll
            for (int nf = 0; nf < 8; ++nf) {
                mma_tf32(acc[0][nf], at[0], bt[nf][0], bt[nf][1]);
                mma_tf32(acc[1][nf], at[1], bt[nf][0], bt[nf][1]);
            }
        }
    }

    #pragma unroll
    for (int mf = 0; mf < 2; ++mf) {
        int r0 = bm + wm + mf * 16 + grp;
        #pragma unroll
        for (int nf = 0; nf < 8; ++nf) {
            int cc = bn + wn + nf * 8 + qid * 2;
            float b0 = 0.0f, b1 = 0.0f;
            if (bias != nullptr) { b0 = bias[cc]; b1 = bias[cc + 1]; }
            float2 v0; v0.x = acc[mf][nf][0] + b0; v0.y = acc[mf][nf][1] + b1;
            float2 v1; v1.x = acc[mf][nf][2] + b0; v1.y = acc[mf][nf][3] + b1;
            *reinterpret_cast<float2*>(C + (size_t)r0 * N + cc) = v0;
            *reinterpret_cast<float2*>(C + (size_t)(r0 + 8) * N + cc) = v1;
        }
    }
}

// ---------------------------------------------------------------------------
// Flash attention on tensor cores (tf32 mma.sync), frag loads batched.
// ---------------------------------------------------------------------------
#define QPAD 68
#define VPAD 72
#define FA_SMEM ((128 * QPAD + 64 * QPAD + 64 * VPAD + 128 * QPAD) * 4)

__global__ __launch_bounds__(256, 2)
void flash_mma(const float* __restrict__ QKV,
               const float* __restrict__ KVc,
               float* __restrict__ Ctx)
{
    extern __shared__ float sm[];
    float* Qs = sm;                       // [128][QPAD]
    float* Ks = Qs + 128 * QPAD;          // [64][QPAD]
    float* Vs = Ks + 64 * QPAD;           // [64][VPAD]
    float* Ps = Vs + 64 * VPAD;           // [128][QPAD]

    const int tid  = threadIdx.x;
    const int wid  = tid >> 5, lane = tid & 31;
    const int grp  = lane >> 2, qid = lane & 3;
    const int wm   = wid * 16;
    const int qt   = blockIdx.x;
    const int h    = blockIdx.y;
    const int b    = blockIdx.z;

    const float scale = 0.125f;

    const float* Qg = QKV + ((size_t)b * N_SZ + (size_t)qt * 128) * C3 + h * D_SZ;
    #pragma unroll
    for (int r = 0; r < 8; ++r) {
        int fid = tid + r * 256;
        int m   = fid >> 4;
        int ds  = (fid & 15) * 4;
        float4 v = *reinterpret_cast<const float4*>(Qg + (size_t)m * C3 + ds);
        float4 w;
        w.x = f2tf32f(v.x * scale);
        w.y = f2tf32f(v.y * scale);
        w.z = f2tf32f(v.z * scale);
        w.w = f2tf32f(v.w * scale);
        *reinterpret_cast<float4*>(&Qs[m * QPAD + ds]) = w;
    }

    float o[8][4];
    #pragma unroll
    for (int nf = 0; nf < 8; ++nf)
        #pragma unroll
        for (int q = 0; q < 4; ++q) o[nf][q] = 0.0f;
    float mi[2] = {-1e30f, -1e30f};
    float li[2] = {0.0f, 0.0f};

    for (int kt = 0; kt < M_KEYS / 64; ++kt) {
        const float* Kg;
        int kstride;
        if (kt < N_SZ / 64) {
            Kg = QKV + ((size_t)b * N_SZ + (size_t)kt * 64) * C3 + C_SZ + h * D_SZ;
            kstride = C3;
        } else {
            Kg = KVc + ((size_t)b * L_SZ + ((size_t)kt * 64 - N_SZ)) * C2 + h * D_SZ;
            kstride = C2;
        }
        const float* Vg = Kg + C_SZ;

        __syncthreads();

        #pragma unroll
        for (int r = 0; r < 4; ++r) {
            int fid = tid + r * 256;
            int n   = fid >> 4;
            int ds  = (fid & 15) * 4;
            float4 kv = *reinterpret_cast<const float4*>(Kg + (size_t)n * kstride + ds);
            float4 kw;
            kw.x = f2tf32f(kv.x); kw.y = f2tf32f(kv.y);
            kw.z = f2tf32f(kv.z); kw.w = f2tf32f(kv.w);
            *reinterpret_cast<float4*>(&Ks[n * QPAD + ds]) = kw;
            float4 vv = *reinterpret_cast<const float4*>(Vg + (size_t)n * kstride + ds);
            float4 vw;
            vw.x = f2tf32f(vv.x); vw.y = f2tf32f(vv.y);
            vw.z = f2tf32f(vv.z); vw.w = f2tf32f(vv.w);
            *reinterpret_cast<float4*>(&Vs[n * VPAD + ds]) = vw;
        }
        __syncthreads();

        // S = Qs @ Ks^T : per-warp m16 x n64 x k64 (loads batched per kk)
        float s[8][4];
        #pragma unroll
        for (int nf = 0; nf < 8; ++nf)
            #pragma unroll
            for (int q = 0; q < 4; ++q) s[nf][q] = 0.0f;

        #pragma unroll
        for (int kk = 0; kk < 8; ++kk) {
            uint32_t a[4];
            const int r0 = (wm + grp) * QPAD + kk * 8 + qid;
            const int r1 = (wm + grp + 8) * QPAD + kk * 8 + qid;
            a[0] = __float_as_uint(Qs[r0]);
            a[1] = __float_as_uint(Qs[r1]);
            a[2] = __float_as_uint(Qs[r0 + 4]);
            a[3] = __float_as_uint(Qs[r1 + 4]);
            uint32_t bt[8][2];
            #pragma unroll
            for (int nf = 0; nf < 8; ++nf) {
                const int cn = (nf * 8 + grp) * QPAD + kk * 8 + qid;
                bt[nf][0] = __float_as_uint(Ks[cn]);
                bt[nf][1] = __float_as_uint(Ks[cn + 4]);
            }
            #pragma unroll
            for (int nf = 0; nf < 8; ++nf)
                mma_tf32(s[nf], a, bt[nf][0], bt[nf][1]);
        }

        // Online softmax
        float mx0 = -1e30f, mx1 = -1e30f;
        #pragma unroll
        for (int nf = 0; nf < 8; ++nf) {
            mx0 = fmaxf(mx0, fmaxf(s[nf][0], s[nf][1]));
            mx1 = fmaxf(mx1, fmaxf(s[nf][2], s[nf][3]));
        }
        #pragma unroll
        for (int off = 1; off < 4; off <<= 1) {
            mx0 = fmaxf(mx0, __shfl_xor_sync(0xffffffffu, mx0, off));
            mx1 = fmaxf(mx1, __shfl_xor_sync(0xffffffffu, mx1, off));
        }
        float mnew0 = fmaxf(mi[0], mx0);
        float mnew1 = fmaxf(mi[1], mx1);
        float corr0 = __expf(mi[0] - mnew0);
        float corr1 = __expf(mi[1] - mnew1);
        float sum0 = 0.0f, sum1 = 0.0f;
        #pragma unroll
        for (int nf = 0; nf < 8; ++nf) {
            s[nf][0] = __expf(s[nf][0] - mnew0);
            s[nf][1] = __expf(s[nf][1] - mnew0);
            s[nf][2] = __expf(s[nf][2] - mnew1);
            s[nf][3] = __expf(s[nf][3] - mnew1);
            sum0 += s[nf][0] + s[nf][1];
            sum1 += s[nf][2] + s[nf][3];
        }
        #pragma unroll
        for (int off = 1; off < 4; off <<= 1) {
            sum0 += __shfl_xor_sync(0xffffffffu, sum0, off);
            sum1 += __shfl_xor_sync(0xffffffffu, sum1, off);
        }
        li[0] = li[0] * corr0 + sum0;
        li[1] = li[1] * corr1 + sum1;
        mi[0] = mnew0;
        mi[1] = mnew1;
        #pragma unroll
        for (int nf = 0; nf < 8; ++nf) {
            o[nf][0] *= corr0;
            o[nf][1] *= corr0;
            o[nf][2] *= corr1;
            o[nf][3] *= corr1;
        }

        // P -> SMEM (tf32-rounded), relayout C-frag -> A-frag
        #pragma unroll
        for (int nf = 0; nf < 8; ++nf) {
            float2 p0, p1;
            p0.x = f2tf32f(s[nf][0]); p0.y = f2tf32f(s[nf][1]);
            p1.x = f2tf32f(s[nf][2]); p1.y = f2tf32f(s[nf][3]);
            *reinterpret_cast<float2*>(&Ps[(wm + grp) * QPAD + nf * 8 + qid * 2]) = p0;
            *reinterpret_cast<float2*>(&Ps[(wm + grp + 8) * QPAD + nf * 8 + qid * 2]) = p1;
        }
        __syncthreads();

        // O += P @ V (loads batched per kk)
        #pragma unroll
        for (int kk = 0; kk < 8; ++kk) {
            uint32_t a[4];
            const int r0 = (wm + grp) * QPAD + kk * 8 + qid;
            const int r1 = (wm + grp + 8) * QPAD + kk * 8 + qid;
            a[0] = __float_as_uint(Ps[r0]);
            a[1] = __float_as_uint(Ps[r1]);
            a[2] = __float_as_uint(Ps[r0 + 4]);
            a[3] = __float_as_uint(Ps[r1 + 4]);
            uint32_t bt[8][2];
            #pragma unroll
            for (int nf = 0; nf < 8; ++nf) {
                const int cb = (kk * 8 + qid) * VPAD + nf * 8 + grp;
                bt[nf][0] = __float_as_uint(Vs[cb]);
                bt[nf][1] = __float_as_uint(Vs[cb + 4 * VPAD]);
            }
            #pragma unroll
            for (int nf = 0; nf < 8; ++nf)
                mma_tf32(o[nf], a, bt[nf][0], bt[nf][1]);
        }
    }

    // Epilogue: normalize, tf32-round (Ctx feeds the tf32 out-proj), store
    const float inv0 = 1.0f / li[0];
    const float inv1 = 1.0f / li[1];
    float* Og = Ctx + ((size_t)b * N_SZ + (size_t)qt * 128) * C_SZ + h * D_SZ;
    #pragma unroll
    for (int nf = 0; nf < 8; ++nf) {
        int col = nf * 8 + qid * 2;
        float2 v0, v1;
        v0.x = f2tf32f(o[nf][0] * inv0); v0.y = f2tf32f(o[nf][1] * inv0);
        v1.x = f2tf32f(o[nf][2] * inv1); v1.y = f2tf32f(o[nf][3] * inv1);
        *reinterpret_cast<float2*>(Og + (size_t)(wm + grp) * C_SZ + col) = v0;
        *reinterpret_cast<float2*>(Og + (size_t)(wm + grp + 8) * C_SZ + col) = v1;
    }
}

// ---------------------------------------------------------------------------
extern "C" void kernel_launch(void* const* d_in, const int* in_sizes, int n_in,
                              void* d_out, int out_size)
{
    const float* x_obj = (const float*)d_in[0];
    const float* x_ctx = (const float*)d_in[1];
    const float* Wq    = (const float*)d_in[2];
    const float* Wkv   = (const float*)d_in[3];
    const float* Wproj = (const float*)d_in[4];
    const float* bproj = (const float*)d_in[5];
    float* out = (float*)d_out;

    float *pXo, *pXc, *pQKV, *pKVc, *pCtx, *pWT, *pWprojT;
    cudaGetSymbolAddress((void**)&pXo,     g_Xo);
    cudaGetSymbolAddress((void**)&pXc,     g_Xc);
    cudaGetSymbolAddress((void**)&pQKV,    g_QKV);
    cudaGetSymbolAddress((void**)&pKVc,    g_KVc);
    cudaGetSymbolAddress((void**)&pCtx,    g_Ctx);
    cudaGetSymbolAddress((void**)&pWT,     g_WT);
    cudaGetSymbolAddress((void**)&pWprojT, g_WprojT);

    cudaFuncSetAttribute(flash_mma, cudaFuncAttributeMaxDynamicSharedMemorySize, FA_SMEM);
    cudaFuncSetAttribute(gemm_mma, cudaFuncAttributeMaxDynamicSharedMemorySize, GEMM_SMEM);

    // Weight transposes + tf32 round ([K,N] -> [N,K])
    transpose_w<<<dim3(C_SZ / 32, C_SZ / 32), dim3(32, 8)>>>(Wq, pWT, C_SZ, C_SZ);
    transpose_w<<<dim3(C2 / 32, C_SZ / 32), dim3(32, 8)>>>(Wkv, pWT + C_SZ * C_SZ, C_SZ, C2);
    transpose_w<<<dim3(C_SZ / 32, C_SZ / 32), dim3(32, 8)>>>(Wproj, pWprojT, C_SZ, C_SZ);

    // tf32 round-copies of activations
    round_copy<<<512, 256>>>((const float4*)x_obj, (float4*)pXo,
                             B_SZ * N_SZ * C_SZ / 4);
    round_copy<<<1024, 256>>>((const float4*)x_ctx, (float4*)pXc,
                              B_SZ * L_SZ * C_SZ / 4);

    // Fused Q+KV projection of x_obj: [2048,1024] x [1024,3072]
    gemm_mma<<<dim3(C3 / 128, 2048 / 128), 256, GEMM_SMEM>>>(
        2048, C3, 1024, pXo, pWT, pQKV, nullptr);
    // KV projection of x_ctx: [8192,1024] x [1024,2048]
    gemm_mma<<<dim3(C2 / 128, 8192 / 128), 256, GEMM_SMEM>>>(
        8192, C2, 1024, pXc, pWT + C_SZ * C_SZ, pKVc, nullptr);

    // Attention (tensor-core tf32 flash)
    flash_mma<<<dim3(N_SZ / 128, H_SZ, B_SZ), 256, FA_SMEM>>>(pQKV, pKVc, pCtx);

    // Output projection + bias
    gemm_mma<<<dim3(1024 / 128, 2048 / 128), 256, GEMM_SMEM>>>(
        2048, 1024, 1024, pCtx, pWprojT, out, bproj);
}